// round 15
// baseline (speedup 1.0000x reference)
#include <cuda_runtime.h>

// ---------------------------------------------------------------------------
// WaveConv2d via perfect-reconstruction shortcut:
//   out = x + IDWT(delta), delta nonzero only at level 4.
// R15: R14 + x-prefetch in final2 + register double-buffered mul2d.
// ---------------------------------------------------------------------------

#define BCv 1024   // B*C

__constant__ float DLO[8] = {
  -0.010597401784997278f,  0.032883011666982945f,  0.030841381835986965f,
  -0.18703481171888114f,  -0.02798376941698385f,   0.6308807679295904f,
   0.7148465705525415f,    0.23037781330885523f };
__constant__ float DHI[8] = {
  -0.23037781330885523f,   0.7148465705525415f,   -0.6308807679295904f,
  -0.02798376941698385f,   0.18703481171888114f,   0.030841381835986965f,
  -0.032883011666982945f, -0.010597401784997278f };

// ---- scratch ----
__device__ float g_ll1[(size_t)BCv*131*131];
__device__ float g_ll2[(size_t)BCv*69*69];
__device__ float g_l4 [(size_t)BCv*4*22*22];
__device__ float g_d4 [(size_t)BCv*4*22*22];
__device__ float g_r3 [(size_t)BCv*69*72];   // rows padded to 72

__device__ __forceinline__ int refl(int j, int N) {
  if (j < 0)  j = -1 - j;
  if (j >= N) j = 2*N - 1 - j;
  return j;
}

// ---------------------------------------------------------------------------
// Level-1 analysis (256x256 -> 131x131, LL only). 32x32 output tile.
// ---------------------------------------------------------------------------
__global__ __launch_bounds__(256)
void afb_ll1_kernel(const float* __restrict__ in, float* __restrict__ out) {
  constexpr int TOY = 32, TOX = 32;
  constexpr int RI = 2*TOY + 6;           // 70
  __shared__ __align__(16) float s_lo[RI][TOX];

  const int bc  = blockIdx.z;
  const int ty0 = blockIdx.y * TOY;
  const int tx0 = blockIdx.x * TOX;
  const int tx = threadIdx.x, ty = threadIdx.y;
  const int t  = ty*32 + tx;
  const float* src = in + bc * 65536;

  const bool interior = (ty0 >= 3) && (2*ty0 + 2*TOY <= 256) &&
                        (tx0 >= 3) && (2*tx0 + 2*TOX <= 256);

  if (interior) {
    const float2* base2 = reinterpret_cast<const float2*>(src + (2*ty0 - 6)*256 + (2*tx0 - 6));
#pragma unroll
    for (int f = t; f < 70*16; f += 256) {
      int r = f >> 4, pr = f & 15;
      const float2* p = base2 + r*128 + 2*pr;
      float2 v0 = p[0], v1 = p[1], v2 = p[2], v3 = p[3], v4 = p[4];
      float lo0 = v0.x*DLO[7] + v0.y*DLO[6] + v1.x*DLO[5] + v1.y*DLO[4]
                + v2.x*DLO[3] + v2.y*DLO[2] + v3.x*DLO[1] + v3.y*DLO[0];
      float lo1 = v1.x*DLO[7] + v1.y*DLO[6] + v2.x*DLO[5] + v2.y*DLO[4]
                + v3.x*DLO[3] + v3.y*DLO[2] + v4.x*DLO[1] + v4.y*DLO[0];
      float2 o2; o2.x = lo0; o2.y = lo1;
      *reinterpret_cast<float2*>(&s_lo[r][2*pr]) = o2;
    }
  } else {
#pragma unroll
    for (int f = t; f < 70*16; f += 256) {
      int r = f >> 4, pr = f & 15;
      int sr = refl(2*ty0 + r - 6, 256);
      const float* row = src + sr * 256;
      int gc = 2*tx0 + 4*pr - 6;
      float v[10];
#pragma unroll
      for (int i = 0; i < 10; i++) v[i] = row[refl(gc + i, 256)];
      float lo0 = 0.f, lo1 = 0.f;
#pragma unroll
      for (int i = 0; i < 8; i++) {
        lo0 += v[i]     * DLO[7 - i];
        lo1 += v[i + 2] * DLO[7 - i];
      }
      float2 o2; o2.x = lo0; o2.y = lo1;
      *reinterpret_cast<float2*>(&s_lo[r][2*pr]) = o2;
    }
  }
  __syncthreads();

  // stage 2: sliding window, 4 consecutive output rows per thread.
  float* dst = out + bc * 17161;
  const int gx = tx0 + tx;
  float v[14];
#pragma unroll
  for (int tt = 0; tt < 14; tt++) v[tt] = s_lo[8*ty + tt][tx];
  if (gx < 131) {
#pragma unroll
    for (int j = 0; j < 4; j++) {
      int oy = ty0 + 4*ty + j;
      if (oy < 131) {
        float acc = 0.f;
#pragma unroll
        for (int tt = 0; tt < 8; tt++) acc += v[2*j + tt] * DLO[7 - tt];
        dst[oy * 131 + gx] = acc;
      }
    }
  }
}

// ---------------------------------------------------------------------------
// Generic LL-only analysis (level 2: 131 -> 69). Block (32,8), 16x32 tiles.
// ---------------------------------------------------------------------------
template<int TOY, int TOX>
__global__ __launch_bounds__(256)
void afb_ll_kernel(const float* __restrict__ in, int inPS,
                   float* __restrict__ out,
                   int H, int W, int OH, int OW) {
  constexpr int RI = 2*TOY + 6;
  constexpr int CI = 2*TOX + 6;
  constexpr int RPT = TOY/8;
  __shared__ float s_in[RI][CI];
  __shared__ float s_lo[RI][TOX];

  const int bc  = blockIdx.z;
  const int ty0 = blockIdx.y * TOY;
  const int tx0 = blockIdx.x * TOX;
  const int tx = threadIdx.x, ty = threadIdx.y;
  const float* src = in + bc * inPS;

  for (int r = ty; r < RI; r += 8) {
    int sr = refl(2*ty0 + r - 6, H);
    const float* row = src + sr * W;
    for (int c = tx; c < CI; c += 32)
      s_in[r][c] = row[refl(2*tx0 + c - 6, W)];
  }
  __syncthreads();

#pragma unroll
  for (int r = ty; r < RI; r += 8) {
    float acc = 0.f;
#pragma unroll
    for (int t = 0; t < 8; t++) acc += s_in[r][2*tx + t] * DLO[7 - t];
    s_lo[r][tx] = acc;
  }
  __syncthreads();

  // stage 2: sliding window, RPT consecutive output rows per thread.
  float* dst = out + bc * OH * OW;
  const int gx = tx0 + tx;
  float v[2*RPT + 6];
#pragma unroll
  for (int tt = 0; tt < 2*RPT + 6; tt++) v[tt] = s_lo[2*RPT*ty + tt][tx];
  if (gx < OW) {
#pragma unroll
    for (int j = 0; j < RPT; j++) {
      int oy = ty0 + RPT*ty + j;
      if (oy < OH) {
        float acc = 0.f;
#pragma unroll
        for (int tt = 0; tt < 8; tt++) acc += v[2*j + tt] * DLO[7 - tt];
        dst[oy * OW + gx] = acc;
      }
    }
  }
}

// ---------------------------------------------------------------------------
// Fused forward levels 3+4: ll2 (BC,69,69) -> l4 (BC,4,22,22). Block/plane.
// ---------------------------------------------------------------------------
__global__ __launch_bounds__(256)
void afb_fused34_kernel(const float* __restrict__ in, float* __restrict__ out) {
  __shared__ float A[69*82];
  __shared__ float Bf[82*39];
  const int bc = blockIdx.x;
  const int tx = threadIdx.x, ty = threadIdx.y;
  const float* src = in + bc * 4761;

  for (int r = ty; r < 69; r += 8)
    for (int c = tx; c < 82; c += 32)
      A[r*82 + c] = src[r*69 + refl(c - 6, 69)];
  __syncthreads();

  for (int pr = ty; pr < 82; pr += 8) {
    int sr = refl(pr - 6, 69);
    const float* arow = &A[sr*82];
    for (int ox = tx; ox < 38; ox += 32) {
      float acc = 0.f;
#pragma unroll
      for (int t = 0; t < 8; t++) acc += arow[2*ox + t] * DLO[7 - t];
      Bf[pr*39 + ox] = acc;
    }
  }
  __syncthreads();

  for (int oy = ty; oy < 38; oy += 8)
    for (int ox = tx; ox < 38; ox += 32) {
      float acc = 0.f;
#pragma unroll
      for (int t = 0; t < 8; t++) acc += Bf[(2*oy + t)*39 + ox] * DLO[7 - t];
      A[oy*50 + 6 + ox] = acc;
    }
  __syncthreads();

  {
    int idx = ty*32 + tx;
    for (int f = idx; f < 38*12; f += 256) {
      int oy = f / 12, k = f - oy*12;
      int c = (k < 6) ? k : (k + 38);
      A[oy*50 + c] = A[oy*50 + 6 + refl(c - 6, 38)];
    }
  }
  __syncthreads();

  for (int pr = ty; pr < 50; pr += 8) {
    int sr = refl(pr - 6, 38);
    const float* arow = &A[sr*50];
    if (tx < 22) {
      float lo = 0.f, hi = 0.f;
#pragma unroll
      for (int t = 0; t < 8; t++) {
        float v = arow[2*tx + t];
        lo += v * DLO[7 - t];
        hi += v * DHI[7 - t];
      }
      Bf[pr*23 + tx] = lo;
      Bf[1150 + pr*23 + tx] = hi;
    }
  }
  __syncthreads();

  float* dst = out + bc * 1936;
  if (tx < 22) {
#pragma unroll
    for (int oy = ty; oy < 22; oy += 8) {
      float ll=0.f, lh=0.f, hl=0.f, hh=0.f;
#pragma unroll
      for (int t = 0; t < 8; t++) {
        float a = Bf[(2*oy + t)*23 + tx];
        float b = Bf[1150 + (2*oy + t)*23 + tx];
        float kl = DLO[7 - t], kh = DHI[7 - t];
        ll += a*kl;  lh += a*kh;  hl += b*kl;  hh += b*kh;
      }
      int o = oy*22 + tx;
      dst[o] = ll;  dst[484 + o] = lh;  dst[968 + o] = hl;  dst[1452 + o] = hh;
    }
  }
}

// ---------------------------------------------------------------------------
// Fused inverse levels 4+3: d4 (BC,4,22,22) -> r3 (BC,69,72 padded).
// ---------------------------------------------------------------------------
__global__ __launch_bounds__(256)
void sfb_fused43_kernel(const float* __restrict__ d4, float* __restrict__ r3) {
  __shared__ float sd[4*484];
  __shared__ float slo[38*23];
  __shared__ float shi[38*23];
  __shared__ float sr4[38*39];
  __shared__ float slo2[69*39];
  const int bc = blockIdx.x;
  const int tx = threadIdx.x, ty = threadIdx.y;
  const int t = ty*32 + tx;
  const float* src = d4 + bc * 1936;

  for (int f = t; f < 1936; f += 256) sd[f] = src[f];
  __syncthreads();

  if (tx < 22) {
#pragma unroll
    for (int jy = ty; jy < 38; jy += 8) {
      int base = jy >> 1, u0 = 1 - (jy & 1);
      float lo = 0.f, hi = 0.f;
#pragma unroll
      for (int m = 0; m < 4; m++) {
        int off = (base + m)*22 + tx;
        float fl = DLO[u0 + 2*m], fh = DHI[u0 + 2*m];
        lo += fl*sd[off]       + fh*sd[484 + off];
        hi += fl*sd[968 + off] + fh*sd[1452 + off];
      }
      slo[jy*23 + tx] = lo;
      shi[jy*23 + tx] = hi;
    }
  }
  __syncthreads();

#pragma unroll
  for (int jy = ty; jy < 38; jy += 8)
    for (int jx = tx; jx < 38; jx += 32) {
      int t0 = 1 - (jx & 1), ib = jx >> 1;
      float acc = 0.f;
#pragma unroll
      for (int m = 0; m < 4; m++)
        acc += DLO[t0 + 2*m]*slo[jy*23 + ib + m] + DHI[t0 + 2*m]*shi[jy*23 + ib + m];
      sr4[jy*39 + jx] = acc;
    }
  __syncthreads();

  for (int jy2 = ty; jy2 < 69; jy2 += 8) {
    int base = jy2 >> 1, u0 = 1 - (jy2 & 1);
    float f0 = DLO[u0], f1 = DLO[u0+2], f2 = DLO[u0+4], f3 = DLO[u0+6];
    for (int i = tx; i < 38; i += 32)
      slo2[jy2*39 + i] = f0*sr4[base*39 + i]     + f1*sr4[(base+1)*39 + i]
                       + f2*sr4[(base+2)*39 + i] + f3*sr4[(base+3)*39 + i];
  }
  __syncthreads();

  float* dst = r3 + bc * 4968;           // padded plane 69*72
  for (int jy2 = ty; jy2 < 69; jy2 += 8)
    for (int jx = tx; jx < 69; jx += 32) {
      int t0 = 1 - (jx & 1), ib = jx >> 1;
      float acc = DLO[t0  ]*slo2[jy2*39 + ib    ]
                + DLO[t0+2]*slo2[jy2*39 + ib + 1]
                + DLO[t0+4]*slo2[jy2*39 + ib + 2]
                + DLO[t0+6]*slo2[jy2*39 + ib + 3];
      dst[jy2*72 + jx] = acc;
    }
}

// ---------------------------------------------------------------------------
// Fused inverse levels 2+1: r3 (BC,69,72) -> out = x + synth (BC,256,256).
// 32-row tiles: grid (8, BCv), block (32,16)=512. x prefetched to registers
// at kernel entry to overlap the smem stage pipeline.
// ---------------------------------------------------------------------------
__global__ __launch_bounds__(512)
void sfb_final2_kernel(const float* __restrict__ r3,
                       const float* __restrict__ x,
                       float* __restrict__ out) {
  __shared__ __align__(16) float s_r3[13][72];
  __shared__ __align__(16) float s_t [19][72];
  __shared__ __align__(16) float s_ll[19][132];
  __shared__ __align__(16) float s_lo[32][132];

  const int bc  = blockIdx.y;
  const int jy0 = blockIdx.x * 32;     // 0..224
  const int q0  = jy0 >> 2;            // r3 row origin: 0..56
  const int tx = threadIdx.x, ty = threadIdx.y;
  const int t = ty*32 + tx;            // 0..511

  const float k0 = DLO[0], k1 = DLO[1], k2 = DLO[2], k3 = DLO[3];
  const float k4 = DLO[4], k5 = DLO[5], k6 = DLO[6], k7 = DLO[7];

  // prefetch x tile into registers (overlaps all smem stages below)
  const float* px = x + bc * 65536;
  float4 xv[2][2];
#pragma unroll
  for (int jj = 0; jj < 2; jj++)
#pragma unroll
    for (int k = 0; k < 2; k++)
      xv[jj][k] = *reinterpret_cast<const float4*>(
          px + (jy0 + ty + 16*jj) * 256 + 128*k + 4*tx);

  // stage A: r3 tile [13][72] via float4 (18 groups/row)
  {
    const float4* g4 = reinterpret_cast<const float4*>(r3 + bc * 4968 + q0 * 72);
    for (int f = t; f < 13*18; f += 512) {
      int r = f / 18, c4 = f - r*18;
      reinterpret_cast<float4*>(&s_r3[r][0])[c4] = g4[r*18 + c4];
    }
  }
  __syncthreads();

  // stage B: vertical L2-synthesis, paired rows (2m, 2m+1 share sources).
  for (int f = t; f < 10*18; f += 512) {
    int m = f / 18, c4 = f - m*18;
    const float4 a = reinterpret_cast<const float4*>(&s_r3[m  ][0])[c4];
    const float4 b = reinterpret_cast<const float4*>(&s_r3[m+1][0])[c4];
    const float4 c = reinterpret_cast<const float4*>(&s_r3[m+2][0])[c4];
    const float4 d = reinterpret_cast<const float4*>(&s_r3[m+3][0])[c4];
    float4 ve;   // even row 2m: u0=1
    ve.x = k1*a.x + k3*b.x + k5*c.x + k7*d.x;
    ve.y = k1*a.y + k3*b.y + k5*c.y + k7*d.y;
    ve.z = k1*a.z + k3*b.z + k5*c.z + k7*d.z;
    ve.w = k1*a.w + k3*b.w + k5*c.w + k7*d.w;
    reinterpret_cast<float4*>(&s_t[2*m][0])[c4] = ve;
    if (m < 9) {
      float4 vo;  // odd row 2m+1: u0=0
      vo.x = k0*a.x + k2*b.x + k4*c.x + k6*d.x;
      vo.y = k0*a.y + k2*b.y + k4*c.y + k6*d.y;
      vo.z = k0*a.z + k2*b.z + k4*c.z + k6*d.z;
      vo.w = k0*a.w + k2*b.w + k4*c.w + k6*d.w;
      reinterpret_cast<float4*>(&s_t[2*m+1][0])[c4] = vo;
    }
  }
  __syncthreads();

  // stage C: horizontal L2-synthesis, even/odd pairs share the 4-tap window
  for (int f = t; f < 19*66; f += 512) {
    int rr = f / 66, q = f - rr*66;
    float a = s_t[rr][q], b = s_t[rr][q+1], c = s_t[rr][q+2], d = s_t[rr][q+3];
    float2 v;
    v.x = k1*a + k3*b + k5*c + k7*d;   // even col 2q
    v.y = k0*a + k2*b + k4*c + k6*d;   // odd col 2q+1
    *reinterpret_cast<float2*>(&s_ll[rr][2*q]) = v;
  }
  __syncthreads();

  // stage 1: vertical L1-synthesis, paired rows, float4. 16 pairs (one per ty).
  {
    int m = ty;  // 0..15
    const float4* r0 = reinterpret_cast<const float4*>(&s_ll[m  ][0]);
    const float4* r1 = reinterpret_cast<const float4*>(&s_ll[m+1][0]);
    const float4* r2 = reinterpret_cast<const float4*>(&s_ll[m+2][0]);
    const float4* r3p = reinterpret_cast<const float4*>(&s_ll[m+3][0]);
    float4* de = reinterpret_cast<float4*>(&s_lo[2*m  ][0]);
    float4* dp = reinterpret_cast<float4*>(&s_lo[2*m+1][0]);
#pragma unroll
    for (int c4 = tx; c4 < 33; c4 += 32) {
      float4 a = r0[c4], b = r1[c4], c = r2[c4], d = r3p[c4];
      float4 ve, vo;
      ve.x = k1*a.x + k3*b.x + k5*c.x + k7*d.x;
      ve.y = k1*a.y + k3*b.y + k5*c.y + k7*d.y;
      ve.z = k1*a.z + k3*b.z + k5*c.z + k7*d.z;
      ve.w = k1*a.w + k3*b.w + k5*c.w + k7*d.w;
      vo.x = k0*a.x + k2*b.x + k4*c.x + k6*d.x;
      vo.y = k0*a.y + k2*b.y + k4*c.y + k6*d.y;
      vo.z = k0*a.z + k2*b.z + k4*c.z + k6*d.z;
      vo.w = k0*a.w + k2*b.w + k4*c.w + k6*d.w;
      de[c4] = ve;
      dp[c4] = vo;
    }
  }
  __syncthreads();

  // stage 2: horizontal L1-synthesis, float4 out with prefetched +x
  float* po = out + bc * 65536;
#pragma unroll
  for (int jj = 0; jj < 2; jj++) {
    int jyl = ty + 16*jj;
    int jy = jy0 + jyl;
    const float2* sp = reinterpret_cast<const float2*>(&s_lo[jyl][0]);
#pragma unroll
    for (int k = 0; k < 2; k++) {
      float2 a = sp[32*k + tx], b = sp[32*k + tx + 1], c2 = sp[32*k + tx + 2];
      float4 v;
      v.x = k1*a.x + k3*a.y + k5*b.x + k7*b.y + xv[jj][k].x;
      v.y = k0*a.x + k2*a.y + k4*b.x + k6*b.y + xv[jj][k].y;
      v.z = k1*a.y + k3*b.x + k5*b.y + k7*c2.x + xv[jj][k].z;
      v.w = k0*a.y + k2*b.x + k4*b.y + k6*c2.x + xv[jj][k].w;
      *reinterpret_cast<float4*>(po + jy * 256 + 128*k + 4*tx) = v;
    }
  }
}

// ---------------------------------------------------------------------------
// Level-4 channel mixing -> delta. Register double-buffered global loads;
// identity subtraction folded into the i-loop.
// grid (16, 4, 8). Block 256: lane = xy (32), g = t>>5 -> b pair, 8 o's.
// ---------------------------------------------------------------------------
__global__ __launch_bounds__(256)
void mul2d_delta_kernel(const float* __restrict__ in,
                        const float* __restrict__ w1,
                        const float* __restrict__ w2,
                        const float* __restrict__ w3,
                        const float* __restrict__ w4,
                        float* __restrict__ outb) {
  const int s   = blockIdx.y;
  const int xy0 = blockIdx.x * 32;
  const int o0  = blockIdx.z * 8;
  const float* W = (s == 0) ? w1 : (s == 1) ? w2 : (s == 2) ? w3 : w4;
  const int t = threadIdx.x;
  const int lane = t & 31;
  const int g    = t >> 5;
  const int xy   = xy0 + lane;
  const bool ok  = xy < 484;

  __shared__ __align__(16) float Ws[8][32][12];
  __shared__ __align__(16) float As[8][32][18];

  // per-thread staging coordinates (fixed across chunks)
  const int wlx = t & 31,  wk = (t >> 5) & 7;                 // W: [ii][wlx][wk]
  const int alx = t & 31,  ab = (t >> 5) & 15;                // A: [ii][alx][ab]
  const int wxg = (xy0 + wlx) < 484 ? (xy0 + wlx) : 483;
  const int axg = (xy0 + alx) < 484 ? (xy0 + alx) : 483;

  float wreg[8], areg[16];

  // prologue: load chunk i0=0 into registers
#pragma unroll
  for (int ii = 0; ii < 8; ii++)
    wreg[ii] = W[(ii*64 + o0 + wk)*484 + wxg];
#pragma unroll
  for (int k = 0; k < 16; k++) {
    int ii = k >> 1, bb = ab + ((k & 1) ? 0 : 0);  // two b's per (ii): ab and ab handled below
    (void)bb; (void)ii;
  }
  // A staging: 8 ii x 16 b x 32 lane = 4096 elems, 16 per thread:
  // thread covers (ii, b) pairs: f = t + 256*k -> ii = f>>9, b = (f>>5)&15.
#pragma unroll
  for (int k = 0; k < 16; k++) {
    int f = t + 256*k;
    int ii = f >> 9, b = (f >> 5) & 15;
    areg[k] = in[((b*64 + ii)*4 + s)*484 + axg];
  }

  float acc[2][8];
#pragma unroll
  for (int j = 0; j < 2; j++)
#pragma unroll
    for (int k = 0; k < 8; k++) acc[j][k] = 0.f;

  for (int i0 = 0; i0 < 64; i0 += 8) {
    __syncthreads();   // previous compute finished reading smem
    // publish current chunk from registers
#pragma unroll
    for (int ii = 0; ii < 8; ii++)
      Ws[ii][wlx][wk] = wreg[ii];
#pragma unroll
    for (int k = 0; k < 16; k++) {
      int f = t + 256*k;
      int ii = f >> 9, b = (f >> 5) & 15;
      As[ii][alx][b] = areg[k];
    }
    __syncthreads();

    // prefetch next chunk (overlaps compute below)
    if (i0 + 8 < 64) {
#pragma unroll
      for (int ii = 0; ii < 8; ii++)
        wreg[ii] = W[((i0 + 8 + ii)*64 + o0 + wk)*484 + wxg];
#pragma unroll
      for (int k = 0; k < 16; k++) {
        int f = t + 256*k;
        int ii = f >> 9, b = (f >> 5) & 15;
        areg[k] = in[((b*64 + (i0 + 8 + ii))*4 + s)*484 + axg];
      }
    }

    // compute on current chunk
#pragma unroll
    for (int ii = 0; ii < 8; ii++) {
      float2 av = *reinterpret_cast<const float2*>(&As[ii][lane][2*g]);
      float4 w0 = *reinterpret_cast<const float4*>(&Ws[ii][lane][0]);
      float4 w1v = *reinterpret_cast<const float4*>(&Ws[ii][lane][4]);
      acc[0][0] += av.x*w0.x;  acc[0][1] += av.x*w0.y;
      acc[0][2] += av.x*w0.z;  acc[0][3] += av.x*w0.w;
      acc[0][4] += av.x*w1v.x; acc[0][5] += av.x*w1v.y;
      acc[0][6] += av.x*w1v.z; acc[0][7] += av.x*w1v.w;
      acc[1][0] += av.y*w0.x;  acc[1][1] += av.y*w0.y;
      acc[1][2] += av.y*w0.z;  acc[1][3] += av.y*w0.w;
      acc[1][4] += av.y*w1v.x; acc[1][5] += av.y*w1v.y;
      acc[1][6] += av.y*w1v.z; acc[1][7] += av.y*w1v.w;
      int io = i0 + ii - o0;
      if (io >= 0 && io < 8) {
        acc[0][io] -= av.x;
        acc[1][io] -= av.y;
      }
    }
  }

  if (ok) {
#pragma unroll
    for (int j = 0; j < 2; j++) {
      int b = 2*g + j;
#pragma unroll
      for (int k = 0; k < 8; k++) {
        int o = o0 + k;
        int idx = ((b*64 + o)*4 + s)*484 + xy;
        outb[idx] = acc[j][k];
      }
    }
  }
}

// ---------------------------------------------------------------------------
extern "C" void kernel_launch(void* const* d_in, const int* in_sizes, int n_in,
                              void* d_out, int out_size) {
  const float* x  = (const float*)d_in[0];
  const float* w1 = (const float*)d_in[1];
  const float* w2 = (const float*)d_in[2];
  const float* w3 = (const float*)d_in[3];
  const float* w4 = (const float*)d_in[4];
  float* out = (float*)d_out;

  float *ll1, *ll2, *l4, *d4, *r3;
  cudaGetSymbolAddress((void**)&ll1, g_ll1);
  cudaGetSymbolAddress((void**)&ll2, g_ll2);
  cudaGetSymbolAddress((void**)&l4,  g_l4);
  cudaGetSymbolAddress((void**)&d4,  g_d4);
  cudaGetSymbolAddress((void**)&r3,  g_r3);

  const dim3 blk(32, 8);

  // forward
  afb_ll1_kernel<<<dim3(5, 5, BCv), blk>>>(x, ll1);
  afb_ll_kernel<16,32><<<dim3(3, 5, BCv), blk>>>(ll1, 17161, ll2, 131, 131, 69, 69);
  afb_fused34_kernel<<<BCv, blk>>>(ll2, l4);

  // level-4 mixing -> delta
  mul2d_delta_kernel<<<dim3(16, 4, 8), 256>>>(l4, w1, w2, w3, w4, d4);

  // inverse
  sfb_fused43_kernel<<<BCv, blk>>>(d4, r3);
  sfb_final2_kernel<<<dim3(8, BCv), dim3(32, 16)>>>(r3, x, out);
}

// round 16
// speedup vs baseline: 1.0474x; 1.0474x over previous
#include <cuda_runtime.h>

// ---------------------------------------------------------------------------
// WaveConv2d via perfect-reconstruction shortcut:
//   out = x + IDWT(delta), delta nonzero only at level 4.
// R16: R14 config (best) + 512-thread fused34/fused43 kernels.
// ---------------------------------------------------------------------------

#define BCv 1024   // B*C

__constant__ float DLO[8] = {
  -0.010597401784997278f,  0.032883011666982945f,  0.030841381835986965f,
  -0.18703481171888114f,  -0.02798376941698385f,   0.6308807679295904f,
   0.7148465705525415f,    0.23037781330885523f };
__constant__ float DHI[8] = {
  -0.23037781330885523f,   0.7148465705525415f,   -0.6308807679295904f,
  -0.02798376941698385f,   0.18703481171888114f,   0.030841381835986965f,
  -0.032883011666982945f, -0.010597401784997278f };

// ---- scratch ----
__device__ float g_ll1[(size_t)BCv*131*131];
__device__ float g_ll2[(size_t)BCv*69*69];
__device__ float g_l4 [(size_t)BCv*4*22*22];
__device__ float g_d4 [(size_t)BCv*4*22*22];
__device__ float g_r3 [(size_t)BCv*69*72];   // rows padded to 72

__device__ __forceinline__ int refl(int j, int N) {
  if (j < 0)  j = -1 - j;
  if (j >= N) j = 2*N - 1 - j;
  return j;
}

// ---------------------------------------------------------------------------
// Level-1 analysis (256x256 -> 131x131, LL only). 32x32 output tile.
// ---------------------------------------------------------------------------
__global__ __launch_bounds__(256)
void afb_ll1_kernel(const float* __restrict__ in, float* __restrict__ out) {
  constexpr int TOY = 32, TOX = 32;
  constexpr int RI = 2*TOY + 6;           // 70
  __shared__ __align__(16) float s_lo[RI][TOX];

  const int bc  = blockIdx.z;
  const int ty0 = blockIdx.y * TOY;
  const int tx0 = blockIdx.x * TOX;
  const int tx = threadIdx.x, ty = threadIdx.y;
  const int t  = ty*32 + tx;
  const float* src = in + bc * 65536;

  const bool interior = (ty0 >= 3) && (2*ty0 + 2*TOY <= 256) &&
                        (tx0 >= 3) && (2*tx0 + 2*TOX <= 256);

  if (interior) {
    const float2* base2 = reinterpret_cast<const float2*>(src + (2*ty0 - 6)*256 + (2*tx0 - 6));
#pragma unroll
    for (int f = t; f < 70*16; f += 256) {
      int r = f >> 4, pr = f & 15;
      const float2* p = base2 + r*128 + 2*pr;
      float2 v0 = p[0], v1 = p[1], v2 = p[2], v3 = p[3], v4 = p[4];
      float lo0 = v0.x*DLO[7] + v0.y*DLO[6] + v1.x*DLO[5] + v1.y*DLO[4]
                + v2.x*DLO[3] + v2.y*DLO[2] + v3.x*DLO[1] + v3.y*DLO[0];
      float lo1 = v1.x*DLO[7] + v1.y*DLO[6] + v2.x*DLO[5] + v2.y*DLO[4]
                + v3.x*DLO[3] + v3.y*DLO[2] + v4.x*DLO[1] + v4.y*DLO[0];
      float2 o2; o2.x = lo0; o2.y = lo1;
      *reinterpret_cast<float2*>(&s_lo[r][2*pr]) = o2;
    }
  } else {
#pragma unroll
    for (int f = t; f < 70*16; f += 256) {
      int r = f >> 4, pr = f & 15;
      int sr = refl(2*ty0 + r - 6, 256);
      const float* row = src + sr * 256;
      int gc = 2*tx0 + 4*pr - 6;
      float v[10];
#pragma unroll
      for (int i = 0; i < 10; i++) v[i] = row[refl(gc + i, 256)];
      float lo0 = 0.f, lo1 = 0.f;
#pragma unroll
      for (int i = 0; i < 8; i++) {
        lo0 += v[i]     * DLO[7 - i];
        lo1 += v[i + 2] * DLO[7 - i];
      }
      float2 o2; o2.x = lo0; o2.y = lo1;
      *reinterpret_cast<float2*>(&s_lo[r][2*pr]) = o2;
    }
  }
  __syncthreads();

  // stage 2: sliding window, 4 consecutive output rows per thread.
  float* dst = out + bc * 17161;
  const int gx = tx0 + tx;
  float v[14];
#pragma unroll
  for (int tt = 0; tt < 14; tt++) v[tt] = s_lo[8*ty + tt][tx];
  if (gx < 131) {
#pragma unroll
    for (int j = 0; j < 4; j++) {
      int oy = ty0 + 4*ty + j;
      if (oy < 131) {
        float acc = 0.f;
#pragma unroll
        for (int tt = 0; tt < 8; tt++) acc += v[2*j + tt] * DLO[7 - tt];
        dst[oy * 131 + gx] = acc;
      }
    }
  }
}

// ---------------------------------------------------------------------------
// Generic LL-only analysis (level 2: 131 -> 69). Block (32,8), 16x32 tiles.
// ---------------------------------------------------------------------------
template<int TOY, int TOX>
__global__ __launch_bounds__(256)
void afb_ll_kernel(const float* __restrict__ in, int inPS,
                   float* __restrict__ out,
                   int H, int W, int OH, int OW) {
  constexpr int RI = 2*TOY + 6;
  constexpr int CI = 2*TOX + 6;
  constexpr int RPT = TOY/8;
  __shared__ float s_in[RI][CI];
  __shared__ float s_lo[RI][TOX];

  const int bc  = blockIdx.z;
  const int ty0 = blockIdx.y * TOY;
  const int tx0 = blockIdx.x * TOX;
  const int tx = threadIdx.x, ty = threadIdx.y;
  const float* src = in + bc * inPS;

  for (int r = ty; r < RI; r += 8) {
    int sr = refl(2*ty0 + r - 6, H);
    const float* row = src + sr * W;
    for (int c = tx; c < CI; c += 32)
      s_in[r][c] = row[refl(2*tx0 + c - 6, W)];
  }
  __syncthreads();

#pragma unroll
  for (int r = ty; r < RI; r += 8) {
    float acc = 0.f;
#pragma unroll
    for (int t = 0; t < 8; t++) acc += s_in[r][2*tx + t] * DLO[7 - t];
    s_lo[r][tx] = acc;
  }
  __syncthreads();

  // stage 2: sliding window, RPT consecutive output rows per thread.
  float* dst = out + bc * OH * OW;
  const int gx = tx0 + tx;
  float v[2*RPT + 6];
#pragma unroll
  for (int tt = 0; tt < 2*RPT + 6; tt++) v[tt] = s_lo[2*RPT*ty + tt][tx];
  if (gx < OW) {
#pragma unroll
    for (int j = 0; j < RPT; j++) {
      int oy = ty0 + RPT*ty + j;
      if (oy < OH) {
        float acc = 0.f;
#pragma unroll
        for (int tt = 0; tt < 8; tt++) acc += v[2*j + tt] * DLO[7 - tt];
        dst[oy * OW + gx] = acc;
      }
    }
  }
}

// ---------------------------------------------------------------------------
// Fused forward levels 3+4: ll2 (BC,69,69) -> l4 (BC,4,22,22). Block/plane.
// Block (32,16) = 512 threads.
// ---------------------------------------------------------------------------
__global__ __launch_bounds__(512)
void afb_fused34_kernel(const float* __restrict__ in, float* __restrict__ out) {
  __shared__ float A[69*82];
  __shared__ float Bf[82*39];
  const int bc = blockIdx.x;
  const int tx = threadIdx.x, ty = threadIdx.y;
  const int t = ty*32 + tx;
  const float* src = in + bc * 4761;

  for (int r = ty; r < 69; r += 16)
    for (int c = tx; c < 82; c += 32)
      A[r*82 + c] = src[r*69 + refl(c - 6, 69)];
  __syncthreads();

  for (int pr = ty; pr < 82; pr += 16) {
    int sr = refl(pr - 6, 69);
    const float* arow = &A[sr*82];
    for (int ox = tx; ox < 38; ox += 32) {
      float acc = 0.f;
#pragma unroll
      for (int tt = 0; tt < 8; tt++) acc += arow[2*ox + tt] * DLO[7 - tt];
      Bf[pr*39 + ox] = acc;
    }
  }
  __syncthreads();

  for (int oy = ty; oy < 38; oy += 16)
    for (int ox = tx; ox < 38; ox += 32) {
      float acc = 0.f;
#pragma unroll
      for (int tt = 0; tt < 8; tt++) acc += Bf[(2*oy + tt)*39 + ox] * DLO[7 - tt];
      A[oy*50 + 6 + ox] = acc;
    }
  __syncthreads();

  {
    for (int f = t; f < 38*12; f += 512) {
      int oy = f / 12, k = f - oy*12;
      int c = (k < 6) ? k : (k + 38);
      A[oy*50 + c] = A[oy*50 + 6 + refl(c - 6, 38)];
    }
  }
  __syncthreads();

  for (int pr = ty; pr < 50; pr += 16) {
    int sr = refl(pr - 6, 38);
    const float* arow = &A[sr*50];
    if (tx < 22) {
      float lo = 0.f, hi = 0.f;
#pragma unroll
      for (int tt = 0; tt < 8; tt++) {
        float v = arow[2*tx + tt];
        lo += v * DLO[7 - tt];
        hi += v * DHI[7 - tt];
      }
      Bf[pr*23 + tx] = lo;
      Bf[1150 + pr*23 + tx] = hi;
    }
  }
  __syncthreads();

  float* dst = out + bc * 1936;
  if (tx < 22 && ty < 11) {
#pragma unroll
    for (int oy = ty; oy < 22; oy += 11) {
      float ll=0.f, lh=0.f, hl=0.f, hh=0.f;
#pragma unroll
      for (int tt = 0; tt < 8; tt++) {
        float a = Bf[(2*oy + tt)*23 + tx];
        float b = Bf[1150 + (2*oy + tt)*23 + tx];
        float kl = DLO[7 - tt], kh = DHI[7 - tt];
        ll += a*kl;  lh += a*kh;  hl += b*kl;  hh += b*kh;
      }
      int o = oy*22 + tx;
      dst[o] = ll;  dst[484 + o] = lh;  dst[968 + o] = hl;  dst[1452 + o] = hh;
    }
  }
}

// ---------------------------------------------------------------------------
// Fused inverse levels 4+3: d4 (BC,4,22,22) -> r3 (BC,69,72 padded).
// Block (32,16) = 512 threads.
// ---------------------------------------------------------------------------
__global__ __launch_bounds__(512)
void sfb_fused43_kernel(const float* __restrict__ d4, float* __restrict__ r3) {
  __shared__ float sd[4*484];
  __shared__ float slo[38*23];
  __shared__ float shi[38*23];
  __shared__ float sr4[38*39];
  __shared__ float slo2[69*39];
  const int bc = blockIdx.x;
  const int tx = threadIdx.x, ty = threadIdx.y;
  const int t = ty*32 + tx;
  const float* src = d4 + bc * 1936;

  for (int f = t; f < 1936; f += 512) sd[f] = src[f];
  __syncthreads();

  if (tx < 22) {
#pragma unroll
    for (int jy = ty; jy < 38; jy += 16) {
      int base = jy >> 1, u0 = 1 - (jy & 1);
      float lo = 0.f, hi = 0.f;
#pragma unroll
      for (int m = 0; m < 4; m++) {
        int off = (base + m)*22 + tx;
        float fl = DLO[u0 + 2*m], fh = DHI[u0 + 2*m];
        lo += fl*sd[off]       + fh*sd[484 + off];
        hi += fl*sd[968 + off] + fh*sd[1452 + off];
      }
      slo[jy*23 + tx] = lo;
      shi[jy*23 + tx] = hi;
    }
  }
  __syncthreads();

#pragma unroll
  for (int jy = ty; jy < 38; jy += 16)
    for (int jx = tx; jx < 38; jx += 32) {
      int t0 = 1 - (jx & 1), ib = jx >> 1;
      float acc = 0.f;
#pragma unroll
      for (int m = 0; m < 4; m++)
        acc += DLO[t0 + 2*m]*slo[jy*23 + ib + m] + DHI[t0 + 2*m]*shi[jy*23 + ib + m];
      sr4[jy*39 + jx] = acc;
    }
  __syncthreads();

  for (int jy2 = ty; jy2 < 69; jy2 += 16) {
    int base = jy2 >> 1, u0 = 1 - (jy2 & 1);
    float f0 = DLO[u0], f1 = DLO[u0+2], f2 = DLO[u0+4], f3 = DLO[u0+6];
    for (int i = tx; i < 38; i += 32)
      slo2[jy2*39 + i] = f0*sr4[base*39 + i]     + f1*sr4[(base+1)*39 + i]
                       + f2*sr4[(base+2)*39 + i] + f3*sr4[(base+3)*39 + i];
  }
  __syncthreads();

  float* dst = r3 + bc * 4968;           // padded plane 69*72
  for (int jy2 = ty; jy2 < 69; jy2 += 16)
    for (int jx = tx; jx < 69; jx += 32) {
      int t0 = 1 - (jx & 1), ib = jx >> 1;
      float acc = DLO[t0  ]*slo2[jy2*39 + ib    ]
                + DLO[t0+2]*slo2[jy2*39 + ib + 1]
                + DLO[t0+4]*slo2[jy2*39 + ib + 2]
                + DLO[t0+6]*slo2[jy2*39 + ib + 3];
      dst[jy2*72 + jx] = acc;
    }
}

// ---------------------------------------------------------------------------
// Fused inverse levels 2+1: r3 (BC,69,72) -> out = x + synth (BC,256,256).
// 32-row tiles: grid (8, BCv), block (32,16)=512. Paired-row vertical stages.
// ---------------------------------------------------------------------------
__global__ __launch_bounds__(512)
void sfb_final2_kernel(const float* __restrict__ r3,
                       const float* __restrict__ x,
                       float* __restrict__ out) {
  __shared__ __align__(16) float s_r3[13][72];
  __shared__ __align__(16) float s_t [19][72];
  __shared__ __align__(16) float s_ll[19][132];
  __shared__ __align__(16) float s_lo[32][132];

  const int bc  = blockIdx.y;
  const int jy0 = blockIdx.x * 32;     // 0..224
  const int q0  = jy0 >> 2;            // r3 row origin: 0..56
  const int tx = threadIdx.x, ty = threadIdx.y;
  const int t = ty*32 + tx;            // 0..511

  const float k0 = DLO[0], k1 = DLO[1], k2 = DLO[2], k3 = DLO[3];
  const float k4 = DLO[4], k5 = DLO[5], k6 = DLO[6], k7 = DLO[7];

  // stage A: r3 tile [13][72] via float4 (18 groups/row)
  {
    const float4* g4 = reinterpret_cast<const float4*>(r3 + bc * 4968 + q0 * 72);
    for (int f = t; f < 13*18; f += 512) {
      int r = f / 18, c4 = f - r*18;
      reinterpret_cast<float4*>(&s_r3[r][0])[c4] = g4[r*18 + c4];
    }
  }
  __syncthreads();

  // stage B: vertical L2-synthesis, paired rows (2m, 2m+1 share sources).
  for (int f = t; f < 10*18; f += 512) {
    int m = f / 18, c4 = f - m*18;
    const float4 a = reinterpret_cast<const float4*>(&s_r3[m  ][0])[c4];
    const float4 b = reinterpret_cast<const float4*>(&s_r3[m+1][0])[c4];
    const float4 c = reinterpret_cast<const float4*>(&s_r3[m+2][0])[c4];
    const float4 d = reinterpret_cast<const float4*>(&s_r3[m+3][0])[c4];
    float4 ve;   // even row 2m: u0=1
    ve.x = k1*a.x + k3*b.x + k5*c.x + k7*d.x;
    ve.y = k1*a.y + k3*b.y + k5*c.y + k7*d.y;
    ve.z = k1*a.z + k3*b.z + k5*c.z + k7*d.z;
    ve.w = k1*a.w + k3*b.w + k5*c.w + k7*d.w;
    reinterpret_cast<float4*>(&s_t[2*m][0])[c4] = ve;
    if (m < 9) {
      float4 vo;  // odd row 2m+1: u0=0
      vo.x = k0*a.x + k2*b.x + k4*c.x + k6*d.x;
      vo.y = k0*a.y + k2*b.y + k4*c.y + k6*d.y;
      vo.z = k0*a.z + k2*b.z + k4*c.z + k6*d.z;
      vo.w = k0*a.w + k2*b.w + k4*c.w + k6*d.w;
      reinterpret_cast<float4*>(&s_t[2*m+1][0])[c4] = vo;
    }
  }
  __syncthreads();

  // stage C: horizontal L2-synthesis, even/odd pairs share the 4-tap window
  for (int f = t; f < 19*66; f += 512) {
    int rr = f / 66, q = f - rr*66;
    float a = s_t[rr][q], b = s_t[rr][q+1], c = s_t[rr][q+2], d = s_t[rr][q+3];
    float2 v;
    v.x = k1*a + k3*b + k5*c + k7*d;   // even col 2q
    v.y = k0*a + k2*b + k4*c + k6*d;   // odd col 2q+1
    *reinterpret_cast<float2*>(&s_ll[rr][2*q]) = v;
  }
  __syncthreads();

  // stage 1: vertical L1-synthesis, paired rows, float4. 16 pairs (one per ty).
  {
    int m = ty;  // 0..15
    const float4* r0 = reinterpret_cast<const float4*>(&s_ll[m  ][0]);
    const float4* r1 = reinterpret_cast<const float4*>(&s_ll[m+1][0]);
    const float4* r2 = reinterpret_cast<const float4*>(&s_ll[m+2][0]);
    const float4* r3p = reinterpret_cast<const float4*>(&s_ll[m+3][0]);
    float4* de = reinterpret_cast<float4*>(&s_lo[2*m  ][0]);
    float4* dp = reinterpret_cast<float4*>(&s_lo[2*m+1][0]);
#pragma unroll
    for (int c4 = tx; c4 < 33; c4 += 32) {
      float4 a = r0[c4], b = r1[c4], c = r2[c4], d = r3p[c4];
      float4 ve, vo;
      ve.x = k1*a.x + k3*b.x + k5*c.x + k7*d.x;
      ve.y = k1*a.y + k3*b.y + k5*c.y + k7*d.y;
      ve.z = k1*a.z + k3*b.z + k5*c.z + k7*d.z;
      ve.w = k1*a.w + k3*b.w + k5*c.w + k7*d.w;
      vo.x = k0*a.x + k2*b.x + k4*c.x + k6*d.x;
      vo.y = k0*a.y + k2*b.y + k4*c.y + k6*d.y;
      vo.z = k0*a.z + k2*b.z + k4*c.z + k6*d.z;
      vo.w = k0*a.w + k2*b.w + k4*c.w + k6*d.w;
      de[c4] = ve;
      dp[c4] = vo;
    }
  }
  __syncthreads();

  // stage 2: horizontal L1-synthesis, float4 out with +x
  float* po = out + bc * 65536;
  const float* px = x + bc * 65536;
#pragma unroll
  for (int jyl = ty; jyl < 32; jyl += 16) {
    int jy = jy0 + jyl;
    const float2* sp = reinterpret_cast<const float2*>(&s_lo[jyl][0]);
#pragma unroll
    for (int k = 0; k < 2; k++) {
      float2 a = sp[32*k + tx], b = sp[32*k + tx + 1], c2 = sp[32*k + tx + 2];
      float4 v;
      v.x = k1*a.x + k3*a.y + k5*b.x + k7*b.y;
      v.y = k0*a.x + k2*a.y + k4*b.x + k6*b.y;
      v.z = k1*a.y + k3*b.x + k5*b.y + k7*c2.x;
      v.w = k0*a.y + k2*b.x + k4*b.y + k6*c2.x;
      int o = jy * 256 + 128*k + 4*tx;
      float4 xv = *reinterpret_cast<const float4*>(px + o);
      v.x += xv.x; v.y += xv.y; v.z += xv.z; v.w += xv.w;
      *reinterpret_cast<float4*>(po + o) = v;
    }
  }
}

// ---------------------------------------------------------------------------
// Level-4 channel mixing -> delta. Vectorized smem tiles; identity
// subtraction folded into the i-loop (no extra global reads).
// grid (16, 4, 8). Block 256: lane = xy (32), g = t>>5 -> b pair, 8 o's.
// ---------------------------------------------------------------------------
__global__ __launch_bounds__(256)
void mul2d_delta_kernel(const float* __restrict__ in,
                        const float* __restrict__ w1,
                        const float* __restrict__ w2,
                        const float* __restrict__ w3,
                        const float* __restrict__ w4,
                        float* __restrict__ outb) {
  const int s   = blockIdx.y;
  const int xy0 = blockIdx.x * 32;
  const int o0  = blockIdx.z * 8;
  const float* W = (s == 0) ? w1 : (s == 1) ? w2 : (s == 2) ? w3 : w4;
  const int t = threadIdx.x;
  const int lane = t & 31;
  const int g    = t >> 5;
  const int xy   = xy0 + lane;
  const bool ok  = xy < 484;

  __shared__ __align__(16) float Ws[8][32][12];
  __shared__ __align__(16) float As[8][32][18];

  float acc[2][8];
#pragma unroll
  for (int j = 0; j < 2; j++)
#pragma unroll
    for (int k = 0; k < 8; k++) acc[j][k] = 0.f;

  for (int i0 = 0; i0 < 64; i0 += 8) {
    __syncthreads();
#pragma unroll
    for (int f = t; f < 8*8*32; f += 256) {
      int lx = f & 31;
      int k  = (f >> 5) & 7;
      int ii = f >> 8;
      int xg = xy0 + lx; xg = xg < 484 ? xg : 483;
      Ws[ii][lx][k] = W[((i0 + ii)*64 + o0 + k)*484 + xg];
    }
#pragma unroll
    for (int f = t; f < 8*16*32; f += 256) {
      int lx = f & 31;
      int b  = (f >> 5) & 15;
      int ii = f >> 9;
      int xg = xy0 + lx; xg = xg < 484 ? xg : 483;
      As[ii][lx][b] = in[((b*64 + (i0 + ii))*4 + s)*484 + xg];
    }
    __syncthreads();
#pragma unroll
    for (int ii = 0; ii < 8; ii++) {
      float2 av = *reinterpret_cast<const float2*>(&As[ii][lane][2*g]);
      float4 w0 = *reinterpret_cast<const float4*>(&Ws[ii][lane][0]);
      float4 w1v = *reinterpret_cast<const float4*>(&Ws[ii][lane][4]);
      acc[0][0] += av.x*w0.x;  acc[0][1] += av.x*w0.y;
      acc[0][2] += av.x*w0.z;  acc[0][3] += av.x*w0.w;
      acc[0][4] += av.x*w1v.x; acc[0][5] += av.x*w1v.y;
      acc[0][6] += av.x*w1v.z; acc[0][7] += av.x*w1v.w;
      acc[1][0] += av.y*w0.x;  acc[1][1] += av.y*w0.y;
      acc[1][2] += av.y*w0.z;  acc[1][3] += av.y*w0.w;
      acc[1][4] += av.y*w1v.x; acc[1][5] += av.y*w1v.y;
      acc[1][6] += av.y*w1v.z; acc[1][7] += av.y*w1v.w;
      // fold delta subtraction: when global i == o0 + io, subtract a[b][i]
      int io = i0 + ii - o0;
      if (io >= 0 && io < 8) {
        acc[0][io] -= av.x;
        acc[1][io] -= av.y;
      }
    }
  }

  if (ok) {
#pragma unroll
    for (int j = 0; j < 2; j++) {
      int b = 2*g + j;
#pragma unroll
      for (int k = 0; k < 8; k++) {
        int o = o0 + k;
        int idx = ((b*64 + o)*4 + s)*484 + xy;
        outb[idx] = acc[j][k];
      }
    }
  }
}

// ---------------------------------------------------------------------------
extern "C" void kernel_launch(void* const* d_in, const int* in_sizes, int n_in,
                              void* d_out, int out_size) {
  const float* x  = (const float*)d_in[0];
  const float* w1 = (const float*)d_in[1];
  const float* w2 = (const float*)d_in[2];
  const float* w3 = (const float*)d_in[3];
  const float* w4 = (const float*)d_in[4];
  float* out = (float*)d_out;

  float *ll1, *ll2, *l4, *d4, *r3;
  cudaGetSymbolAddress((void**)&ll1, g_ll1);
  cudaGetSymbolAddress((void**)&ll2, g_ll2);
  cudaGetSymbolAddress((void**)&l4,  g_l4);
  cudaGetSymbolAddress((void**)&d4,  g_d4);
  cudaGetSymbolAddress((void**)&r3,  g_r3);

  const dim3 blk(32, 8);
  const dim3 blk16(32, 16);

  // forward
  afb_ll1_kernel<<<dim3(5, 5, BCv), blk>>>(x, ll1);
  afb_ll_kernel<16,32><<<dim3(3, 5, BCv), blk>>>(ll1, 17161, ll2, 131, 131, 69, 69);
  afb_fused34_kernel<<<BCv, blk16>>>(ll2, l4);

  // level-4 mixing -> delta
  mul2d_delta_kernel<<<dim3(16, 4, 8), 256>>>(l4, w1, w2, w3, w4, d4);

  // inverse
  sfb_fused43_kernel<<<BCv, blk16>>>(d4, r3);
  sfb_final2_kernel<<<dim3(8, BCv), blk16>>>(r3, x, out);
}